// round 2
// baseline (speedup 1.0000x reference)
#include <cuda_runtime.h>
#include <cstdint>

#define W_DIM   21504
#define NSEG    64
#define NELEM   8192
#define TILE_R  32
#define MAX_TILES 320     // 8192/32 + 63 partials max
#define TPB     128
#define RPAD    34        // padded row stride in smem (even -> 8B aligned pairs)

typedef unsigned long long u64;

// ---------------- device globals (scratch; no allocations allowed) ----------
__device__ int  d_starts[NSEG + 1];
__device__ int2 d_tiles[MAX_TILES];   // {row_start, segment}
__device__ int  d_ntiles;

// ---------------- packed f32x2 helpers (Blackwell) --------------------------
__device__ __forceinline__ u64 pack2(float a) {
    u64 r; asm("mov.b64 %0, {%1, %1};" : "=l"(r) : "f"(a)); return r;
}
__device__ __forceinline__ u64 fma2(u64 a, u64 b, u64 c) {
    u64 d; asm("fma.rn.f32x2 %0, %1, %2, %3;" : "=l"(d) : "l"(a), "l"(b), "l"(c));
    return d;
}
__device__ __forceinline__ u64 lds64(unsigned a) {
    u64 v; asm volatile("ld.shared.b64 %0, [%1];" : "=l"(v) : "r"(a)); return v;
}
__device__ __forceinline__ void unpack2(u64 v, float& lo, float& hi) {
    asm("mov.b64 {%0, %1}, %2;" : "=f"(lo), "=f"(hi) : "l"(v));
}

// ---------------- prekernel: segment starts + tile work list ----------------
__global__ void seg_kernel(const int* __restrict__ counts) {
    __shared__ int s_start[NSEG + 1];
    __shared__ int s_tb[NSEG + 1];
    int t = threadIdx.x;
    if (t == 0) {
        int a = 0, tb = 0;
        #pragma unroll 8
        for (int g = 0; g < NSEG; g++) {
            s_start[g] = a;
            s_tb[g]    = tb;
            int c = counts[g];
            a  += c;
            tb += (c + TILE_R - 1) >> 5;
        }
        s_start[NSEG] = a;
        s_tb[NSEG]    = tb;
        d_ntiles      = tb;
        d_starts[NSEG] = a;
    }
    __syncthreads();
    if (t < NSEG) {
        d_starts[t] = s_start[t];
        int start = s_start[t];
        int tb    = s_tb[t];
        int nt    = s_tb[t + 1] - tb;
        for (int k = 0; k < nt; k++)
            d_tiles[tb + k] = make_int2(start + TILE_R * k, t);
    }
}

// ---------------- main compute -----------------------------------------------
// Per tile (32 rows, one segment g, one irrep):
//   y[r, o, i] = coeff * sum_m x[r, m, i] * w[g, WOFF + m*MUL + o]
// Thread geometry: NO = MUL/4 lanes own 4 consecutive o's; NRG = 128/NO row
// groups; each thread accumulates NRP row-PAIRS packed in f32x2.
template <int MUL, int DIM, int WOFF>
__device__ __forceinline__ void run_irrep(const float* __restrict__ x,
                                          const float* __restrict__ w,
                                          float* __restrict__ y,
                                          int tile, float coeff,
                                          float* xs) {
    if (tile >= d_ntiles) return;
    const int2 tt   = d_tiles[tile];
    const int row0  = tt.x;
    const int g     = tt.y;
    int nrows = d_starts[g + 1] - row0;
    if (nrows > TILE_R) nrows = TILE_R;

    constexpr int CH = MUL * DIM;          // floats per row for this irrep

    // ---- stage x tile into smem, transposed to [channel][row] ----
    const float* xt = x + (size_t)row0 * CH;
    for (int e = threadIdx.x; e < TILE_R * CH; e += TPB) {
        int r = e / CH;
        int c = e - r * CH;                // c = m*DIM + i
        float v = 0.f;
        if (r < nrows) v = xt[e];          // predicated load, no OOB
        xs[c * RPAD + r] = v;
    }
    __syncthreads();

    constexpr int NO  = MUL / 4;           // o4 lanes
    constexpr int NRG = TPB / NO;          // row groups
    constexpr int RPG = TILE_R / NRG;      // rows per group
    constexpr int NRP = RPG / 2;           // row pairs per thread

    const int t     = threadIdx.x;
    const int o4    = t & (NO - 1);
    const int rg    = t / NO;
    const int obase = o4 * 4;
    const int rbase = rg * RPG;

    const float* wseg = w + (size_t)g * W_DIM + WOFF + obase;

    u64 acc[NRP][DIM][4];
    #pragma unroll
    for (int p = 0; p < NRP; p++)
        #pragma unroll
        for (int i = 0; i < DIM; i++)
            #pragma unroll
            for (int j = 0; j < 4; j++) acc[p][i][j] = 0ull;

    const unsigned xsa = (unsigned)__cvta_generic_to_shared(xs) + rbase * 4u;

    #pragma unroll 2
    for (int m = 0; m < MUL; m++) {
        const float4 wv = *reinterpret_cast<const float4*>(wseg + m * MUL);
        u64 w2[4];
        w2[0] = pack2(wv.x); w2[1] = pack2(wv.y);
        w2[2] = pack2(wv.z); w2[3] = pack2(wv.w);
        #pragma unroll
        for (int i = 0; i < DIM; i++) {
            const unsigned a0 = xsa + (unsigned)((m * DIM + i) * RPAD) * 4u;
            #pragma unroll
            for (int p = 0; p < NRP; p++) {
                const u64 x2 = lds64(a0 + 8u * p);   // two adjacent rows packed
                #pragma unroll
                for (int j = 0; j < 4; j++)
                    acc[p][i][j] = fma2(x2, w2[j], acc[p][i][j]);
            }
        }
    }

    // ---- epilogue: scale, unpack row pairs, coalesced float4 stores ----
    float* yt = y + (size_t)row0 * CH + obase * DIM;
    #pragma unroll
    for (int p = 0; p < NRP; p++) {
        const int r0 = rbase + 2 * p;
        float b0[4 * DIM], b1[4 * DIM];
        #pragma unroll
        for (int i = 0; i < DIM; i++)
            #pragma unroll
            for (int j = 0; j < 4; j++) {
                float lo, hi;
                unpack2(acc[p][i][j], lo, hi);
                b0[j * DIM + i] = lo * coeff;
                b1[j * DIM + i] = hi * coeff;
            }
        if (r0 < nrows) {
            float* dst = yt + (size_t)r0 * CH;
            #pragma unroll
            for (int q = 0; q < DIM; q++)
                *reinterpret_cast<float4*>(dst + 4 * q) =
                    make_float4(b0[4 * q], b0[4 * q + 1], b0[4 * q + 2], b0[4 * q + 3]);
        }
        if (r0 + 1 < nrows) {
            float* dst = yt + (size_t)(r0 + 1) * CH;
            #pragma unroll
            for (int q = 0; q < DIM; q++)
                *reinterpret_cast<float4*>(dst + 4 * q) =
                    make_float4(b1[4 * q], b1[4 * q + 1], b1[4 * q + 2], b1[4 * q + 3]);
        }
    }
}

__global__ __launch_bounds__(TPB)
void lin_main(const float* __restrict__ x0, const float* __restrict__ x1,
              const float* __restrict__ x2, const float* __restrict__ w,
              float* __restrict__ out) {
    __shared__ float xs[64 * 3 * RPAD];    // 26112 B, max over irreps
    const int b = blockIdx.x;
    if (b < MAX_TILES) {
        // 128x0e: coeff = 1/(8*sqrt(128))
        run_irrep<128, 1, 0>(x0, w, out, b, 0.011048543456039806f, xs);
    } else if (b < 2 * MAX_TILES) {
        // 64x1o: coeff = 1/64
        run_irrep<64, 3, 16384>(x1, w, out + (size_t)NELEM * 128,
                                b - MAX_TILES, 0.015625f, xs);
    } else {
        // 32x2e: coeff = 1/(8*sqrt(32))
        run_irrep<32, 5, 20480>(x2, w, out + (size_t)NELEM * (128 + 192),
                                b - 2 * MAX_TILES, 0.022097086912079613f, xs);
    }
}

extern "C" void kernel_launch(void* const* d_in, const int* in_sizes, int n_in,
                              void* d_out, int out_size) {
    const float* x0     = (const float*)d_in[0];
    const float* x1     = (const float*)d_in[1];
    const float* x2     = (const float*)d_in[2];
    const float* w      = (const float*)d_in[3];
    const int*   counts = (const int*)d_in[4];
    float*       out    = (float*)d_out;

    seg_kernel<<<1, NSEG>>>(counts);
    lin_main<<<3 * MAX_TILES, TPB>>>(x0, x1, x2, w, out);
}